// round 15
// baseline (speedup 1.0000x reference)
#include <cuda_runtime.h>
#include <cuda_fp16.h>
#include <math.h>

// SlowROIPool R15:
//  - prep fused into convert kernel (blocks 0..1567 convert fp32->fp16 padded
//    planes; block 1568 runs ROI prep) -> one less serialized launch.
//  - roipool: 4 channels per block (cquad). Grid 1024 = 8 img x 32 cquad x
//    4 roi-quarters. Narrow ROIs: 8 H4-lanes x 4 channels (no shfl). Wide:
//    2 groups x 16 H4-lanes, 2 channel chains per lane. Per-ROI overhead
//    amortized over 4 channels.
// images: [8,128,56,56] f32, rois: [512,4] f32, roi_idx: [512] i32,
// out: [512,128,7,7] f32.

#define OUT_D 7
#define ROWH4    16                 // H4 (8-byte) units per plane row (64 halves)
#define PLANE_H4 (56 * ROWH4)       // H4 units per (b,c) plane
#define CMCH 232                    // colmax channel stride in __half2 words
                                    // (7*32=224 +8: stagger banks across channels)

// fp16 planes: 1024 planes x 56 rows x 64 halves (+pad for q=15 overread)
__device__ __align__(16) unsigned long long g_plane[1024 * PLANE_H4 + 32];

__device__ int        g_meta[512];  // roi | cp0q<<16 | narrow<<24
__device__ ulonglong2 g_ybin[512];  // {ysP, nP}: byte i = ys / row-count of y-bin i
__device__ ulonglong2 g_xbin[512];  // {xsP, xeP}: byte j = half-index bounds (frac3-based)
__device__ int        g_start[9];   // per-image segment starts

// ---- fused: fp32->fp16 conversion (blocks 0..1567) + ROI prep (block 1568) ----
__global__ void prep_convert_kernel(const float* __restrict__ images,
                                    const float* __restrict__ rois,
                                    const int*   __restrict__ roi_idx)
{
    if (blockIdx.x < 1568) {
        // convert: 1568 blocks x 512 threads = 802816 float4 (exact)
        const int j = blockIdx.x * 512 + threadIdx.x;
        float4 v = reinterpret_cast<const float4*>(images)[j];
        const int r  = j / 14;                      // global row = plane*56 + y
        const int c4 = j - r * 14;
        __half2 lo = __floats2half2_rn(v.x, v.y);
        __half2 hi = __floats2half2_rn(v.z, v.w);
        uint2 w;
        w.x = *reinterpret_cast<unsigned*>(&lo);
        w.y = *reinterpret_cast<unsigned*>(&hi);
        reinterpret_cast<uint2*>(g_plane)[r * ROWH4 + c4] = w;
        return;
    }

    // ---- prep (block 1568, 512 threads) ----
    __shared__ int cnt[8];
    __shared__ int base[8];
    __shared__ int hist[8][128];
    const int tid = threadIdx.x;
    if (tid < 8) cnt[tid] = 0;
    for (int i = tid; i < 8 * 128; i += 512) (&hist[0][0])[i] = 0;
    __syncthreads();
    const int img = roi_idx[tid];
    atomicAdd(&cnt[img], 1);
    __syncthreads();
    if (tid == 0) {
        int acc = 0;
        for (int i = 0; i < 8; i++) { base[i] = acc; g_start[i] = acc; acc += cnt[i]; }
        g_start[8] = acc;
    }
    __syncthreads();

    const float4 box = reinterpret_cast<const float4*>(rois)[tid];
    // Match jnp: fp32 floor/ceil then int cast.
    const int x1 = (int)floorf(box.x * 56.0f);
    const int y1 = (int)floorf(box.y * 56.0f);
    const int x2 = (int)ceilf (box.z * 56.0f);
    const int y2 = (int)ceilf (box.w * 56.0f);
    const int Lx = x2 - x1, Ly = y2 - y1;
    const int frac3 = x1 & 3;             // offset from 4-half-aligned base
    const int cp0q  = x1 >> 2;            // H4-unit base within row (<= 6)

    unsigned long long ysP = 0, nP = 0, xsP = 0, xeP = 0;
    for (int j = 0; j < OUT_D; j++) {
        const int ys = y1 + (j * Ly) / 7;
        const int ye = y1 + ((j + 1) * Ly + 6) / 7;     // ceil div, ye > ys
        ysP |= (unsigned long long)ys << (8 * j);
        nP  |= (unsigned long long)(ye - ys) << (8 * j);
        const int xs = (j * Lx) / 7 + frac3;            // half-index in colmax
        const int xe = ((j + 1) * Lx + 6) / 7 + frac3;  // <= 59 < 64
        xsP |= (unsigned long long)xs << (8 * j);
        xeP |= (unsigned long long)xe << (8 * j);
    }
    const int narrow = (frac3 + Lx) <= 32;
    // cost key: rows, wides cost ~2x narrows -> bias them first. key < 128.
    const int key = Ly + (narrow ? 0 : 57);

    atomicAdd(&hist[img][key], 1);
    __syncthreads();
    if (tid < 8) {                        // descending prefix (big keys first)
        int off = 0;
        for (int v = 127; v >= 0; v--) { int t = hist[tid][v]; hist[tid][v] = off; off += t; }
    }
    __syncthreads();
    const int pos = base[img] + atomicAdd(&hist[img][key], 1);
    g_meta[pos] = tid | (cp0q << 16) | (narrow << 24);
    g_ybin[pos] = make_ulonglong2(ysP, nP);
    g_xbin[pos] = make_ulonglong2(xsP, xeP);
}

__device__ __forceinline__ int bget(unsigned long long p, int i) {
    return (int)((p >> (8 * i)) & 0xFF);
}

struct H4 { __half2 a, b; };

__device__ __forceinline__ H4 ldh4(const uint2* p) {
    uint2 t = __ldg(p);
    H4 h;
    h.a = *reinterpret_cast<__half2*>(&t.x);
    h.b = *reinterpret_cast<__half2*>(&t.y);
    return h;
}
__device__ __forceinline__ H4 h4max(H4 x, H4 y) {
    x.a = __hmax2(x.a, y.a);
    x.b = __hmax2(x.b, y.b);
    return x;
}

__global__ __launch_bounds__(256, 7)
void roipool_kernel(float* __restrict__ out)
{
    // colmax: per warp, 4 channels x 7 bins x 32 words, channel stride 232
    __shared__ __align__(16) __half2 colmaxA[8 * 4 * CMCH];   // 29696 B

    const int bid = blockIdx.x;           // ((b*32 + cq) << 2) | quarter
    const int qt  = bid & 3;
    const int bcq = bid >> 2;
    const int b   = bcq >> 5;
    const int c0  = (bcq & 31) * 4;

    const int tid  = threadIdx.x;
    const int warp = tid >> 5;
    const int lane = tid & 31;

    const uint2* pl = reinterpret_cast<const uint2*>(g_plane)
                      + (size_t)(b * 128 + c0) * PLANE_H4;

    __half2* cmwarp = colmaxA + warp * (4 * CMCH);

    const int s = g_start[b];
    const int e = g_start[b + 1];

    // 32-way deal over the descending-sorted segment (LPT balance).
    for (int k = s + warp * 4 + qt; k < e; k += 32) {
        const int meta = g_meta[k];
        const ulonglong2 yb = g_ybin[k];
        const int cp0q   = (meta >> 16) & 0xFF;
        const int narrow =  meta >> 24;

        if (narrow) {
            // 8 H4-lanes per channel (32 halves), 4 channels across the warp.
            const int q  = lane & 7;
            const int ch = lane >> 3;
            const uint2* baseq = pl + ch * PLANE_H4 + cp0q + q;
            __half2* cmc = cmwarp + ch * CMCH + 2 * q;
            #pragma unroll
            for (int i = 0; i < OUT_D; i++) {
                const int ys = bget(yb.x, i);
                const int n  = bget(yb.y, i);
                const uint2* ptr = baseq + ys * ROWH4;
                H4 m = ldh4(ptr);                         // peel (bin non-empty)
                int rem = n - 1;
                ptr += ROWH4;
                while (rem >= 2) {                        // unroll 2
                    m = h4max(h4max(m, ldh4(ptr)), ldh4(ptr + ROWH4));
                    ptr += 2 * ROWH4;
                    rem -= 2;
                }
                if (rem) m = h4max(m, ldh4(ptr));
                cmc[i * 32]     = m.a;
                cmc[i * 32 + 1] = m.b;
            }
        } else {
            // 16 H4-lanes per group (64 halves); 2 channel chains per lane.
            const int q = lane & 15;
            const int g = lane >> 4;
            const uint2* baseq = pl + g * PLANE_H4 + cp0q + q;
            __half2* cmc = cmwarp + g * CMCH + 2 * q;
            #pragma unroll
            for (int i = 0; i < OUT_D; i++) {
                const int ys = bget(yb.x, i);
                const int n  = bget(yb.y, i);
                const uint2* ptr = baseq + ys * ROWH4;
                H4 m0 = ldh4(ptr);
                H4 m1 = ldh4(ptr + 2 * PLANE_H4);
                int rem = n - 1;
                ptr += ROWH4;
                while (rem >= 2) {                        // unroll 2, 2 chains
                    m0 = h4max(h4max(m0, ldh4(ptr)), ldh4(ptr + ROWH4));
                    m1 = h4max(h4max(m1, ldh4(ptr + 2 * PLANE_H4)),
                               ldh4(ptr + 2 * PLANE_H4 + ROWH4));
                    ptr += 2 * ROWH4;
                    rem -= 2;
                }
                if (rem) {
                    m0 = h4max(m0, ldh4(ptr));
                    m1 = h4max(m1, ldh4(ptr + 2 * PLANE_H4));
                }
                cmc[i * 32]                = m0.a;
                cmc[i * 32 + 1]            = m0.b;
                cmc[2 * CMCH + i * 32]     = m1.a;
                cmc[2 * CMCH + i * 32 + 1] = m1.b;
            }
        }
        __syncwarp();

        // ---- Pass 2: 49 outputs x 4 channels; shared index math ----
        const ulonglong2 xb = g_xbin[k];
        const int r = meta & 0xFFFF;
        float* outr = out + ((size_t)r * 128 + c0) * (OUT_D * OUT_D);
        #pragma unroll
        for (int bs = 0; bs < 64; bs += 32) {
            const int o = bs + lane;
            if (o < OUT_D * OUT_D) {
                const int i  = (o * 37) >> 8;             // o/7 for o<49
                const int j  = o - i * 7;
                const int xs = bget(xb.x, j);
                const int xe = bget(xb.y, j);
                const __half* cA = reinterpret_cast<const __half*>(cmwarp + i * 32);
                __half m0 = cA[xs];
                __half m1 = cA[2 * CMCH + xs];
                __half m2 = cA[4 * CMCH + xs];
                __half m3 = cA[6 * CMCH + xs];
                for (int x = xs + 1; x < xe; x++) {
                    m0 = __hmax(m0, cA[x]);
                    m1 = __hmax(m1, cA[2 * CMCH + x]);
                    m2 = __hmax(m2, cA[4 * CMCH + x]);
                    m3 = __hmax(m3, cA[6 * CMCH + x]);
                }
                outr[o]      = __half2float(m0);
                outr[o + 49] = __half2float(m1);
                outr[o + 98] = __half2float(m2);
                outr[o + 147] = __half2float(m3);
            }
        }
        __syncwarp();   // protect colmax before next ROI's pass 1
    }
}

extern "C" void kernel_launch(void* const* d_in, const int* in_sizes, int n_in,
                              void* d_out, int out_size)
{
    const float* images  = (const float*)d_in[0];   // [8,128,56,56]
    const float* rois    = (const float*)d_in[1];   // [512,4]
    const int*   roi_idx = (const int*)  d_in[2];   // [512]
    float*       out     = (float*)d_out;           // [512,128,7,7]

    // blocks 0..1567: convert (1568*512 = 802816 float4, exact); block 1568: prep
    prep_convert_kernel<<<1569, 512>>>(images, rois, roi_idx);
    roipool_kernel<<<8 * 32 * 4, 256>>>(out);
}